// round 1
// baseline (speedup 1.0000x reference)
#include <cuda_runtime.h>
#include <math.h>

#define T_TOK   8192
#define DMODEL  2048
#define NHEAD   16
#define DHEAD   128
#define SEQ     1024
#define NSEQ    8
#define PBS     256
#define NPB     64
#define BLKS_PER_SEQ 4   // SEQ / PBS

// ---------------- scratch (device globals; no runtime allocation) ----------
__device__ float g_q[(size_t)T_TOK * DMODEL];
__device__ float g_k[(size_t)T_TOK * DMODEL];
__device__ float g_v[(size_t)T_TOK * DMODEL];
__device__ float g_attn[(size_t)T_TOK * DMODEL];
__device__ float g_cos[SEQ * 64];
__device__ float g_sin[SEQ * 64];
__device__ int   g_inv[NPB];

// ---------------- GEMM:  C[M,N] = A[M,K] @ B[N,K]^T  (NT, all row-major) ----
#define GBM 128
#define GBN 128
#define GBK 16

__global__ __launch_bounds__(256, 2)
void gemm_nt(const float* __restrict__ A, const float* __restrict__ B,
             float* __restrict__ C, int M, int N, int K)
{
    __shared__ float As[GBK][GBM + 4];
    __shared__ float Bs[GBK][GBN + 4];

    const int tid = threadIdx.x;
    const int bn  = blockIdx.x;
    const int bm  = blockIdx.y;

    const float* Ab = A + (size_t)bm * GBM * K;
    const float* Bb = B + (size_t)bn * GBN * K;

    const int ty  = tid >> 4;          // 0..15
    const int tx  = tid & 15;          // 0..15
    const int row = ty * 8;
    const int col = tx * 8;

    float acc[8][8];
#pragma unroll
    for (int i = 0; i < 8; i++)
#pragma unroll
        for (int j = 0; j < 8; j++) acc[i][j] = 0.f;

    for (int k0 = 0; k0 < K; k0 += GBK) {
#pragma unroll
        for (int it = 0; it < 2; it++) {
            int lin = tid + it * 256;          // 0..511 float4 slots
            int m   = lin >> 2;                // 0..127
            int kq  = (lin & 3) << 2;          // 0,4,8,12
            float4 a = *(const float4*)(Ab + (size_t)m * K + k0 + kq);
            As[kq + 0][m] = a.x; As[kq + 1][m] = a.y;
            As[kq + 2][m] = a.z; As[kq + 3][m] = a.w;
            float4 b = *(const float4*)(Bb + (size_t)m * K + k0 + kq);
            Bs[kq + 0][m] = b.x; Bs[kq + 1][m] = b.y;
            Bs[kq + 2][m] = b.z; Bs[kq + 3][m] = b.w;
        }
        __syncthreads();

#pragma unroll
        for (int k = 0; k < GBK; k++) {
            float a[8], b[8];
            *(float4*)(a)     = *(const float4*)&As[k][row];
            *(float4*)(a + 4) = *(const float4*)&As[k][row + 4];
            *(float4*)(b)     = *(const float4*)&Bs[k][col];
            *(float4*)(b + 4) = *(const float4*)&Bs[k][col + 4];
#pragma unroll
            for (int i = 0; i < 8; i++)
#pragma unroll
                for (int j = 0; j < 8; j++) acc[i][j] += a[i] * b[j];
        }
        __syncthreads();
    }

#pragma unroll
    for (int i = 0; i < 8; i++) {
        float* Cr = C + (size_t)(bm * GBM + row + i) * N + bn * GBN + col;
        float4 r0 = make_float4(acc[i][0], acc[i][1], acc[i][2], acc[i][3]);
        float4 r1 = make_float4(acc[i][4], acc[i][5], acc[i][6], acc[i][7]);
        *(float4*)(Cr)     = r0;
        *(float4*)(Cr + 4) = r1;
    }
}

// ---------------- trig table: cos/sin[pos][j], j = 0..63 --------------------
__global__ void trig_kernel()
{
    int idx = blockIdx.x * blockDim.x + threadIdx.x;   // SEQ*64
    int j   = idx & 63;
    int pos = idx >> 6;
    // inv_freq = 10000^(-(2j)/128)
    float inv_freq = expf(-(float)(2 * j) * (1.0f / 128.0f) * logf(10000.0f));
    float ang = (float)pos * inv_freq;
    float s, c;
    sincosf(ang, &s, &c);
    g_cos[idx] = c;
    g_sin[idx] = s;
}

// ---------------- RoPE in-place on g_q and g_k ------------------------------
__global__ void rope_kernel()
{
    int idx = blockIdx.x * blockDim.x + threadIdx.x;   // T*H*64
    int j = idx & 63;
    int h = (idx >> 6) & 15;
    int t = idx >> 10;
    int pos = t & (SEQ - 1);
    float c = g_cos[pos * 64 + j];
    float s = g_sin[pos * 64 + j];
    size_t o0 = (size_t)t * DMODEL + h * DHEAD + j;
    size_t o1 = o0 + 64;
    float q0 = g_q[o0], q1 = g_q[o1];
    g_q[o0] = q0 * c - q1 * s;
    g_q[o1] = q1 * c + q0 * s;
    float k0 = g_k[o0], k1 = g_k[o1];
    g_k[o0] = k0 * c - k1 * s;
    g_k[o1] = k1 * c + k0 * s;
}

// ---------------- inverse block table ---------------------------------------
__global__ void build_inv(const int* __restrict__ bt)
{
    int i = threadIdx.x;
    if (i < NPB) g_inv[i] = -1;
    __syncthreads();
    if (i < NSEQ * BLKS_PER_SEQ) {
        int p = bt[i];
        g_inv[p] = i;                 // encodes b*BLKS_PER_SEQ + lb
    }
}

// ---------------- paged-KV cache gather (writes every element once) ---------
__global__ void cache_gather(const float* __restrict__ cache_in,
                             float* __restrict__ cache_out)
{
    size_t i4 = (size_t)blockIdx.x * 256 + threadIdx.x;  // float4 index
    size_t i  = i4 * 4;
    int dh  = (int)(i & 127);
    size_t r = i >> 7;
    int off = (int)(r & 255); r >>= 8;
    int h   = (int)(r & 15);  r >>= 4;
    int kv  = (int)(r & 1);
    int p   = (int)(r >> 1);

    int code = g_inv[p];
    float4 val;
    if (code < 0) {
        val = *(const float4*)(cache_in + i);
    } else {
        int b  = code >> 2;       // /BLKS_PER_SEQ
        int lb = code & 3;
        int t  = b * SEQ + lb * PBS + off;
        const float* src = (kv == 0 ? g_k : g_v) + (size_t)t * DMODEL + h * DHEAD + dh;
        val = *(const float4*)src;
    }
    *(float4*)(cache_out + i) = val;
}

// ---------------- causal flash attention (fp32) ------------------------------
// grid: (S/64, B*H), 256 threads, dynamic smem
__global__ void flash_attn(const float* __restrict__ q, const float* __restrict__ k,
                           const float* __restrict__ v, float* __restrict__ o)
{
    extern __shared__ float sm[];
    float* Qs = sm;                  // 64 x 132
    float* Ks = Qs + 64 * 132;       // 64 x 132
    float* Vs = Ks + 64 * 132;       // 64 x 132
    float* Ps = Vs + 64 * 132;       // 64 x 68

    const int qt = blockIdx.x;
    const int bh = blockIdx.y;
    const int b  = bh >> 4;
    const int h  = bh & 15;
    const int tid = threadIdx.x;
    const int ty = tid >> 4;         // 0..15 -> queries
    const int tx = tid & 15;         // 0..15 -> keys / dh
    const int rq = ty * 4;
    const int ck = tx * 4;
    const int cd = tx * 8;
    const float scale = 0.08838834764831845f;  // 1/sqrt(128)

    const size_t base = ((size_t)b * SEQ) * DMODEL + (size_t)h * DHEAD;

    // load Q tile
#pragma unroll
    for (int it = 0; it < 8; it++) {
        int lin = tid + it * 256;      // 0..2047 float4 slots
        int r = lin >> 5;              // 0..63
        int d = (lin & 31) << 2;       // 0..124
        *(float4*)&Qs[r * 132 + d] =
            *(const float4*)(q + base + (size_t)(qt * 64 + r) * DMODEL + d);
    }

    float m_i[4], l_i[4], oa[4][8];
#pragma unroll
    for (int i = 0; i < 4; i++) {
        m_i[i] = -1e30f; l_i[i] = 0.f;
#pragma unroll
        for (int c = 0; c < 8; c++) oa[i][c] = 0.f;
    }
    __syncthreads();

    for (int kt = 0; kt <= qt; kt++) {
        // load K, V tiles
#pragma unroll
        for (int it = 0; it < 8; it++) {
            int lin = tid + it * 256;
            int r = lin >> 5;
            int d = (lin & 31) << 2;
            size_t g = base + (size_t)(kt * 64 + r) * DMODEL + d;
            *(float4*)&Ks[r * 132 + d] = *(const float4*)(k + g);
            *(float4*)&Vs[r * 132 + d] = *(const float4*)(v + g);
        }
        __syncthreads();

        // scores 4x4
        float s[4][4];
#pragma unroll
        for (int i = 0; i < 4; i++)
#pragma unroll
            for (int j = 0; j < 4; j++) s[i][j] = 0.f;

#pragma unroll 8
        for (int d0 = 0; d0 < DHEAD; d0 += 4) {
            float4 qv[4], kv4[4];
#pragma unroll
            for (int i = 0; i < 4; i++) qv[i]  = *(float4*)&Qs[(rq + i) * 132 + d0];
#pragma unroll
            for (int j = 0; j < 4; j++) kv4[j] = *(float4*)&Ks[(ck + j) * 132 + d0];
#pragma unroll
            for (int i = 0; i < 4; i++)
#pragma unroll
                for (int j = 0; j < 4; j++)
                    s[i][j] += qv[i].x * kv4[j].x + qv[i].y * kv4[j].y +
                               qv[i].z * kv4[j].z + qv[i].w * kv4[j].w;
        }

        // scale + causal mask (only diagonal tile needs masking)
#pragma unroll
        for (int i = 0; i < 4; i++)
#pragma unroll
            for (int j = 0; j < 4; j++) {
                float val = s[i][j] * scale;
                if (kt == qt && (ck + j) > (rq + i)) val = -1e30f;
                s[i][j] = val;
            }

        // online softmax update per row
#pragma unroll
        for (int i = 0; i < 4; i++) {
            float rm = fmaxf(fmaxf(s[i][0], s[i][1]), fmaxf(s[i][2], s[i][3]));
#pragma unroll
            for (int off = 8; off > 0; off >>= 1)
                rm = fmaxf(rm, __shfl_xor_sync(0xffffffffu, rm, off));
            float mn = fmaxf(m_i[i], rm);
            float alpha = __expf(m_i[i] - mn);
            float rs = 0.f;
#pragma unroll
            for (int j = 0; j < 4; j++) {
                float p = __expf(s[i][j] - mn);
                Ps[(rq + i) * 68 + ck + j] = p;
                rs += p;
            }
#pragma unroll
            for (int off = 8; off > 0; off >>= 1)
                rs += __shfl_xor_sync(0xffffffffu, rs, off);
            l_i[i] = l_i[i] * alpha + rs;
            m_i[i] = mn;
#pragma unroll
            for (int c = 0; c < 8; c++) oa[i][c] *= alpha;
        }
        __syncthreads();

        // O += P @ V
#pragma unroll 4
        for (int kk = 0; kk < 64; kk++) {
            float4 v0 = *(float4*)&Vs[kk * 132 + cd];
            float4 v1 = *(float4*)&Vs[kk * 132 + cd + 4];
#pragma unroll
            for (int i = 0; i < 4; i++) {
                float p = Ps[(rq + i) * 68 + kk];
                oa[i][0] += p * v0.x; oa[i][1] += p * v0.y;
                oa[i][2] += p * v0.z; oa[i][3] += p * v0.w;
                oa[i][4] += p * v1.x; oa[i][5] += p * v1.y;
                oa[i][6] += p * v1.z; oa[i][7] += p * v1.w;
            }
        }
        __syncthreads();
    }

    // normalize + write
#pragma unroll
    for (int i = 0; i < 4; i++) {
        float inv = 1.0f / l_i[i];
        float4 r0 = make_float4(oa[i][0] * inv, oa[i][1] * inv, oa[i][2] * inv, oa[i][3] * inv);
        float4 r1 = make_float4(oa[i][4] * inv, oa[i][5] * inv, oa[i][6] * inv, oa[i][7] * inv);
        float* dst = o + base + (size_t)(qt * 64 + rq + i) * DMODEL + cd;
        *(float4*)(dst)     = r0;
        *(float4*)(dst + 4) = r1;
    }
}

// ---------------- launch -----------------------------------------------------
extern "C" void kernel_launch(void* const* d_in, const int* in_sizes, int n_in,
                              void* d_out, int out_size)
{
    const float* x   = (const float*)d_in[0];
    const float* Wq  = (const float*)d_in[1];
    const float* Wk  = (const float*)d_in[2];
    const float* Wv  = (const float*)d_in[3];
    const float* Wo  = (const float*)d_in[4];
    const float* cin = (const float*)d_in[5];
    const int*   bt  = (const int*)d_in[7];

    float* out       = (float*)d_out;
    float* cache_out = out + (size_t)T_TOK * DMODEL;

    float *q, *k, *v, *attn;
    cudaGetSymbolAddress((void**)&q,    g_q);
    cudaGetSymbolAddress((void**)&k,    g_k);
    cudaGetSymbolAddress((void**)&v,    g_v);
    cudaGetSymbolAddress((void**)&attn, g_attn);

    const size_t fa_smem = (size_t)(3 * 64 * 132 + 64 * 68) * sizeof(float); // 118784
    cudaFuncSetAttribute(flash_attn, cudaFuncAttributeMaxDynamicSharedMemorySize,
                         (int)fa_smem);

    dim3 ggrid(DMODEL / GBN, T_TOK / GBM);   // (16, 64)

    // QKV projections
    gemm_nt<<<ggrid, 256>>>(x, Wq, q, T_TOK, DMODEL, DMODEL);
    gemm_nt<<<ggrid, 256>>>(x, Wk, k, T_TOK, DMODEL, DMODEL);
    gemm_nt<<<ggrid, 256>>>(x, Wv, v, T_TOK, DMODEL, DMODEL);

    // trig table + inverse block table (independent, cheap)
    trig_kernel<<<(SEQ * 64) / 256, 256>>>();
    build_inv<<<1, 64>>>(bt);

    // RoPE on q, k
    rope_kernel<<<(T_TOK * NHEAD * 64) / 256, 256>>>();

    // paged KV cache (gather form; writes every element exactly once)
    if ((size_t)out_size >= (size_t)T_TOK * DMODEL + (size_t)NPB * 2 * NHEAD * PBS * DHEAD) {
        cache_gather<<<((size_t)NPB * 2 * NHEAD * PBS * DHEAD / 4) / 256, 256>>>(cin, cache_out);
    }

    // causal flash attention
    flash_attn<<<dim3(SEQ / 64, NSEQ * NHEAD), 256, fa_smem>>>(q, k, v, attn);

    // output projection
    gemm_nt<<<ggrid, 256>>>(attn, Wo, out, T_TOK, DMODEL, DMODEL);
}

// round 3
// speedup vs baseline: 1.9556x; 1.9556x over previous
#include <cuda_runtime.h>
#include <cuda_bf16.h>
#include <math.h>
#include <stdint.h>

#define T_TOK   8192
#define DMODEL  2048
#define NHEAD   16
#define DHEAD   128
#define SEQ     1024
#define NSEQ    8
#define PBS     256
#define NPB     64
#define BLKS_PER_SEQ 4
#define WSZ     (DMODEL * DMODEL)

// Device-pass arch gate: tcgen05 only exists in the 'a'-target compilation.
#if defined(__CUDA_ARCH__)
#  if defined(__CUDA_ARCH_FEAT_SM103_ALL) || defined(__CUDA_ARCH_FEAT_SM100_ALL) || \
      (defined(__CUDA_ARCH_SPECIFIC__) && (__CUDA_ARCH_SPECIFIC__ >= 1000))
#    define HAS_TCGEN05 1
#  endif
#endif

// ---------------- scratch (device globals; no runtime allocation) ----------
__device__ __align__(16) float g_q[(size_t)T_TOK * DMODEL];
__device__ __align__(16) float g_k[(size_t)T_TOK * DMODEL];
__device__ __align__(16) float g_v[(size_t)T_TOK * DMODEL];
__device__ __align__(16) float g_attn[(size_t)T_TOK * DMODEL];
__device__ __align__(16) float g_cos[SEQ * 64];
__device__ __align__(16) float g_sin[SEQ * 64];
__device__ int   g_inv[NPB];

// bf16 split operands (tcgen05 path only)
__device__ __align__(16) __nv_bfloat16 gx_hi[(size_t)T_TOK * DMODEL];
__device__ __align__(16) __nv_bfloat16 gx_lo[(size_t)T_TOK * DMODEL];
__device__ __align__(16) __nv_bfloat16 gw_hi[(size_t)4 * WSZ];
__device__ __align__(16) __nv_bfloat16 gw_lo[(size_t)4 * WSZ];
__device__ __align__(16) __nv_bfloat16 ga_hi[(size_t)T_TOK * DMODEL];
__device__ __align__(16) __nv_bfloat16 ga_lo[(size_t)T_TOK * DMODEL];

// =================== PTX helpers (arch-portable ones) ======================
__device__ __forceinline__ uint32_t smem_u32(const void* p) {
    uint32_t a;
    asm("{ .reg .u64 t; cvta.to.shared.u64 t, %1; cvt.u32.u64 %0, t; }"
        : "=r"(a) : "l"(p));
    return a;
}

__device__ __forceinline__ uint32_t elect_one_pred() {
    uint32_t pred;
    asm volatile(
        "{\n\t.reg .pred p;\n\telect.sync _|p, 0xFFFFFFFF;\n\t"
        "selp.b32 %0, 1, 0, p;\n\t}"
        : "=r"(pred));
    return pred;
}

#define MBAR_INIT(addr, cnt) \
    asm volatile("mbarrier.init.shared.b64 [%0], %1;" :: "r"(addr), "r"(cnt) : "memory")

#define MBAR_WAIT(addr, parity) do {                                          \
    uint32_t _mb = (addr); uint32_t _p = (parity); uint32_t _done;            \
    asm volatile("{\n\t.reg .pred p;\n\t"                                     \
        "mbarrier.try_wait.parity.acquire.cta.shared::cta.b64 p, [%1], %2;\n\t"\
        "selp.b32 %0, 1, 0, p;\n\t}"                                          \
        : "=r"(_done) : "r"(_mb), "r"(_p) : "memory");                        \
    if (!_done) {                                                             \
        asm volatile("{\n\t.reg .pred P1;\n\t"                                \
            "WL_%=:\n\t"                                                      \
            "mbarrier.try_wait.parity.acquire.cta.shared::cta.b64 P1, [%0], %1, 0x989680;\n\t" \
            "@P1 bra.uni WD_%=;\n\t"                                          \
            "bra.uni WL_%=;\n\t"                                              \
            "WD_%=:\n\t}"                                                     \
            :: "r"(_mb), "r"(_p) : "memory");                                 \
    }                                                                         \
} while (0)

__device__ __forceinline__ void cp16(uint32_t s, const void* g) {
    asm volatile("cp.async.cg.shared.global [%0], [%1], 16;" :: "r"(s), "l"(g));
}
__device__ __forceinline__ void cp_arrive_noinc(uint32_t mbar) {
    asm volatile("cp.async.mbarrier.arrive.noinc.shared::cta.b64 [%0];"
                 :: "r"(mbar) : "memory");
}

// =================== tcgen05-only helpers ==================================
#if defined(HAS_TCGEN05)
#define TC_ALLOC(sa, n) \
    asm volatile("tcgen05.alloc.cta_group::1.sync.aligned.shared::cta.b32 [%0], %1;" \
                 :: "r"((uint32_t)(sa)), "r"((uint32_t)(n)) : "memory")
#define TC_DEALLOC(t, n) \
    asm volatile("tcgen05.dealloc.cta_group::1.sync.aligned.b32 %0, %1;" :: "r"(t), "r"((uint32_t)(n)))
#define TC_RELINQ() \
    asm volatile("tcgen05.relinquish_alloc_permit.cta_group::1.sync.aligned;")
#define TC_COMMIT(mb) \
    asm volatile("tcgen05.commit.cta_group::1.mbarrier::arrive::one.shared::cluster.b64 [%0];" \
                 :: "r"((uint32_t)(mb)) : "memory")
#define TC_FENCE_AFTER() asm volatile("tcgen05.fence::after_thread_sync;" ::: "memory")
#define TC_WAIT_LD() asm volatile("tcgen05.wait::ld.sync.aligned;" ::: "memory")

#define TC_LD_X32(r, addr) \
    asm volatile("tcgen05.ld.sync.aligned.32x32b.x32.b32 " \
        "{%0, %1, %2, %3, %4, %5, %6, %7, %8, %9, %10, %11, %12, %13, %14, %15, " \
        " %16, %17, %18, %19, %20, %21, %22, %23, %24, %25, %26, %27, %28, %29, %30, %31}, [%32];" \
        : "=r"((r)[0]),  "=r"((r)[1]),  "=r"((r)[2]),  "=r"((r)[3]), \
          "=r"((r)[4]),  "=r"((r)[5]),  "=r"((r)[6]),  "=r"((r)[7]), \
          "=r"((r)[8]),  "=r"((r)[9]),  "=r"((r)[10]), "=r"((r)[11]), \
          "=r"((r)[12]), "=r"((r)[13]), "=r"((r)[14]), "=r"((r)[15]), \
          "=r"((r)[16]), "=r"((r)[17]), "=r"((r)[18]), "=r"((r)[19]), \
          "=r"((r)[20]), "=r"((r)[21]), "=r"((r)[22]), "=r"((r)[23]), \
          "=r"((r)[24]), "=r"((r)[25]), "=r"((r)[26]), "=r"((r)[27]), \
          "=r"((r)[28]), "=r"((r)[29]), "=r"((r)[30]), "=r"((r)[31]) \
        : "r"(addr))

__device__ __forceinline__ void mma_ss_bf16(uint32_t d, uint64_t ad, uint64_t bd,
                                            uint32_t idesc, uint32_t en) {
    asm volatile(
        "{\n\t.reg .pred p;\n\tsetp.ne.u32 p, %5, 0;\n\t"
        "tcgen05.mma.cta_group::1.kind::f16 [%0], %1, %2, %3, {%4, %4, %4, %4}, p;\n\t}"
        :: "r"(d), "l"(ad), "l"(bd), "r"(idesc), "r"(0u), "r"(en) : "memory");
}
#endif // HAS_TCGEN05

static constexpr uint64_t DESC_BASE_SW128 =
    (uint64_t(2)  << 61) | (uint64_t(1) << 46) | (uint64_t(64) << 32) | (uint64_t(1) << 16);
#define MK_DESC(a) (DESC_BASE_SW128 | ((uint64_t)((a) >> 4) & 0x3FFF))

// =================== split: fp32 -> bf16 hi + bf16 lo (tc path only) =======
__global__ void split_kernel(const float* __restrict__ src,
                             __nv_bfloat16* __restrict__ hi,
                             __nv_bfloat16* __restrict__ lo, int n4)
{
#if !defined(HAS_TCGEN05)
    return;   // fallback mode: tcgen05 GEMM never runs, split output unused
#else
    int i = blockIdx.x * blockDim.x + threadIdx.x;
    if (i >= n4) return;
    float4 v = ((const float4*)src)[i];
    __nv_bfloat16 h0 = __float2bfloat16(v.x);
    __nv_bfloat16 h1 = __float2bfloat16(v.y);
    __nv_bfloat16 h2 = __float2bfloat16(v.z);
    __nv_bfloat16 h3 = __float2bfloat16(v.w);
    __nv_bfloat16 l0 = __float2bfloat16(v.x - __bfloat162float(h0));
    __nv_bfloat16 l1 = __float2bfloat16(v.y - __bfloat162float(h1));
    __nv_bfloat16 l2 = __float2bfloat16(v.z - __bfloat162float(h2));
    __nv_bfloat16 l3 = __float2bfloat16(v.w - __bfloat162float(h3));
    uint2 hp, lp;
    unsigned short* hs = (unsigned short*)&hp;
    unsigned short* ls = (unsigned short*)&lp;
    hs[0] = reinterpret_cast<unsigned short&>(h0);
    hs[1] = reinterpret_cast<unsigned short&>(h1);
    hs[2] = reinterpret_cast<unsigned short&>(h2);
    hs[3] = reinterpret_cast<unsigned short&>(h3);
    ls[0] = reinterpret_cast<unsigned short&>(l0);
    ls[1] = reinterpret_cast<unsigned short&>(l1);
    ls[2] = reinterpret_cast<unsigned short&>(l2);
    ls[3] = reinterpret_cast<unsigned short&>(l3);
    ((uint2*)hi)[i] = hp;
    ((uint2*)lo)[i] = lp;
#endif
}

// =================== tcgen05 3xBF16 GEMM (a-pass only) =====================
// C[8192,2048] = A[8192,2048] @ B[2048,2048]^T, A=Ahi+Alo, B=Bhi+Blo
// CTA tile M=128, N=256; K in chunks of 64 (128B SW128 rows); 2-stage cp.async
#define STAGE_BYTES 98304u
#define BAR_OFF     196608u
#define GEMM_SMEM   196672u

static constexpr uint32_t IDESC_BF16 =
    (1u << 4) | (1u << 7) | (1u << 10) | ((256u / 8) << 17) | ((128u / 16) << 24);

__global__ __launch_bounds__(128, 1)
void gemm3x(const __nv_bfloat16* __restrict__ Ahi, const __nv_bfloat16* __restrict__ Alo,
            const __nv_bfloat16* __restrict__ Bhi, const __nv_bfloat16* __restrict__ Blo,
            float* __restrict__ C)
{
#if !defined(HAS_TCGEN05)
    return;   // non-'a' compilation: gemm_nt fallback does the work instead
#else
    extern __shared__ char smem[];
    const uint32_t sb = smem_u32(smem);
    const int tid = threadIdx.x;
    const int bn = blockIdx.x;   // 0..7
    const int bm = blockIdx.y;   // 0..63

    const uint32_t FULL  = sb + BAR_OFF;
    const uint32_t EMPTY = sb + BAR_OFF + 16;
    const uint32_t DONE  = sb + BAR_OFF + 32;
    const uint32_t TPTR  = sb + BAR_OFF + 40;

    if (tid == 0) {
        MBAR_INIT(FULL + 0, 96);  MBAR_INIT(FULL + 8, 96);
        MBAR_INIT(EMPTY + 0, 1);  MBAR_INIT(EMPTY + 8, 1);
        MBAR_INIT(DONE, 1);
    }
    if (tid < 32) TC_ALLOC(TPTR, 256);
    __syncthreads();
    uint32_t tmem;
    asm volatile("ld.shared.b32 %0, [%1];" : "=r"(tmem) : "r"(TPTR));

    if (tid < 32) {
        if (elect_one_pred()) {
            for (int kt = 0; kt < 32; kt++) {
                const int st = kt & 1;
                MBAR_WAIT(FULL + st * 8, (kt >> 1) & 1);
                asm volatile("fence.proxy.async.shared::cta;" ::: "memory");
                const uint32_t so = sb + st * STAGE_BYTES;
                const uint64_t ah = MK_DESC(so);
                const uint64_t al = MK_DESC(so + 16384u);
                const uint64_t bh = MK_DESC(so + 32768u);
                const uint64_t bl = MK_DESC(so + 65536u);
#pragma unroll
                for (int ks = 0; ks < 4; ks++) {
                    mma_ss_bf16(tmem, ah + ks * 2, bh + ks * 2, IDESC_BF16,
                                (kt | ks) ? 1u : 0u);
                    mma_ss_bf16(tmem, al + ks * 2, bh + ks * 2, IDESC_BF16, 1u);
                    mma_ss_bf16(tmem, ah + ks * 2, bl + ks * 2, IDESC_BF16, 1u);
                }
                TC_COMMIT(EMPTY + st * 8);
            }
            TC_COMMIT(DONE);
        }
    } else {
        const int t = tid - 32;
        for (int lk = 0; lk < 32; lk++) {
            const int st = lk & 1;
            if (lk >= 2) MBAR_WAIT(EMPTY + st * 8, ((lk >> 1) - 1) & 1);
            const uint32_t so = sb + st * STAGE_BYTES;
            const int k0 = lk * 64;
            if (t < 32) {
                const int r0 = t * 4;
#pragma unroll
                for (int rr = 0; rr < 4; rr++) {
                    const int r = r0 + rr;
                    const size_t gofs = (size_t)(bm * 128 + r) * DMODEL + k0;
                    const __nv_bfloat16* gh = Ahi + gofs;
                    const __nv_bfloat16* gl = Alo + gofs;
                    const uint32_t srow = so + r * 128;
#pragma unroll
                    for (int c = 0; c < 8; c++) {
                        const uint32_t sw = (uint32_t)((c ^ (r & 7)) << 4);
                        cp16(srow + sw,          gh + c * 8);
                        cp16(srow + 16384u + sw, gl + c * 8);
                    }
                }
            } else {
                const int r0 = (t - 32) * 4;
#pragma unroll
                for (int rr = 0; rr < 4; rr++) {
                    const int r = r0 + rr;
                    const size_t gofs = (size_t)(bn * 256 + r) * DMODEL + k0;
                    const __nv_bfloat16* gh = Bhi + gofs;
                    const __nv_bfloat16* gl = Blo + gofs;
                    const uint32_t srow = so + 32768u + r * 128;
#pragma unroll
                    for (int c = 0; c < 8; c++) {
                        const uint32_t sw = (uint32_t)((c ^ (r & 7)) << 4);
                        cp16(srow + sw,          gh + c * 8);
                        cp16(srow + 32768u + sw, gl + c * 8);
                    }
                }
            }
            cp_arrive_noinc(FULL + st * 8);
        }
    }

    __syncthreads();
    MBAR_WAIT(DONE, 0);
    TC_FENCE_AFTER();

    const int w = tid >> 5, l = tid & 31;
    const size_t row = (size_t)(bm * 128 + w * 32 + l);
#pragma unroll 1
    for (int cb = 0; cb < 256; cb += 32) {
        uint32_t r[32];
        TC_LD_X32(r, tmem + cb);
        TC_WAIT_LD();
        float* dst = C + row * DMODEL + bn * 256 + cb;
#pragma unroll
        for (int j = 0; j < 32; j += 4) {
            float4 v = make_float4(__uint_as_float(r[j]),     __uint_as_float(r[j + 1]),
                                   __uint_as_float(r[j + 2]), __uint_as_float(r[j + 3]));
            *(float4*)(dst + j) = v;
        }
    }

    __syncthreads();
    if (tid < 32) {
        TC_RELINQ();
        TC_DEALLOC(tmem, 256);
    }
#endif // HAS_TCGEN05
}

// =================== fp32 SIMT GEMM fallback (non-'a' pass only) ============
#define GBM 128
#define GBN 128
#define GBK 16

__global__ __launch_bounds__(256, 2)
void gemm_nt(const float* __restrict__ A, const float* __restrict__ B,
             float* __restrict__ C, int M, int N, int K)
{
#if defined(HAS_TCGEN05)
    return;   // 'a' pass: gemm3x does the work instead
#else
    __shared__ float As[GBK][GBM + 4];
    __shared__ float Bs[GBK][GBN + 4];

    const int tid = threadIdx.x;
    const int bn  = blockIdx.x;
    const int bm  = blockIdx.y;

    const float* Ab = A + (size_t)bm * GBM * K;
    const float* Bb = B + (size_t)bn * GBN * K;

    const int ty  = tid >> 4;
    const int tx  = tid & 15;
    const int row = ty * 8;
    const int col = tx * 8;

    float acc[8][8];
#pragma unroll
    for (int i = 0; i < 8; i++)
#pragma unroll
        for (int j = 0; j < 8; j++) acc[i][j] = 0.f;

    for (int k0 = 0; k0 < K; k0 += GBK) {
#pragma unroll
        for (int it = 0; it < 2; it++) {
            int lin = tid + it * 256;
            int m   = lin >> 2;
            int kq  = (lin & 3) << 2;
            float4 a = *(const float4*)(Ab + (size_t)m * K + k0 + kq);
            As[kq + 0][m] = a.x; As[kq + 1][m] = a.y;
            As[kq + 2][m] = a.z; As[kq + 3][m] = a.w;
            float4 b = *(const float4*)(Bb + (size_t)m * K + k0 + kq);
            Bs[kq + 0][m] = b.x; Bs[kq + 1][m] = b.y;
            Bs[kq + 2][m] = b.z; Bs[kq + 3][m] = b.w;
        }
        __syncthreads();

#pragma unroll
        for (int k = 0; k < GBK; k++) {
            float a[8], b[8];
            *(float4*)(a)     = *(const float4*)&As[k][row];
            *(float4*)(a + 4) = *(const float4*)&As[k][row + 4];
            *(float4*)(b)     = *(const float4*)&Bs[k][col];
            *(float4*)(b + 4) = *(const float4*)&Bs[k][col + 4];
#pragma unroll
            for (int i = 0; i < 8; i++)
#pragma unroll
                for (int j = 0; j < 8; j++) acc[i][j] += a[i] * b[j];
        }
        __syncthreads();
    }

#pragma unroll
    for (int i = 0; i < 8; i++) {
        float* Cr = C + (size_t)(bm * GBM + row + i) * N + bn * GBN + col;
        *(float4*)(Cr)     = make_float4(acc[i][0], acc[i][1], acc[i][2], acc[i][3]);
        *(float4*)(Cr + 4) = make_float4(acc[i][4], acc[i][5], acc[i][6], acc[i][7]);
    }
#endif
}

// =================== trig table ============================================
__global__ void trig_kernel()
{
    int idx = blockIdx.x * blockDim.x + threadIdx.x;
    int j   = idx & 63;
    int pos = idx >> 6;
    float inv_freq = expf(-(float)(2 * j) * (1.0f / 128.0f) * logf(10000.0f));
    float ang = (float)pos * inv_freq;
    float s, c;
    sincosf(ang, &s, &c);
    g_cos[idx] = c;
    g_sin[idx] = s;
}

// =================== RoPE in-place on g_q, g_k =============================
__global__ void rope_kernel()
{
    int idx = blockIdx.x * blockDim.x + threadIdx.x;
    int j = idx & 63;
    int h = (idx >> 6) & 15;
    int t = idx >> 10;
    int pos = t & (SEQ - 1);
    float c = g_cos[pos * 64 + j];
    float s = g_sin[pos * 64 + j];
    size_t o0 = (size_t)t * DMODEL + h * DHEAD + j;
    size_t o1 = o0 + 64;
    float q0 = g_q[o0], q1 = g_q[o1];
    g_q[o0] = q0 * c - q1 * s;
    g_q[o1] = q1 * c + q0 * s;
    float k0 = g_k[o0], k1 = g_k[o1];
    g_k[o0] = k0 * c - k1 * s;
    g_k[o1] = k1 * c + k0 * s;
}

// =================== inverse block table ===================================
__global__ void build_inv(const int* __restrict__ bt)
{
    int i = threadIdx.x;
    if (i < NPB) g_inv[i] = -1;
    __syncthreads();
    if (i < NSEQ * BLKS_PER_SEQ) {
        int p = bt[i];
        g_inv[p] = i;
    }
}

// =================== paged-KV cache gather =================================
__global__ void cache_gather(const float* __restrict__ cache_in,
                             float* __restrict__ cache_out)
{
    size_t i4 = (size_t)blockIdx.x * 256 + threadIdx.x;
    size_t i  = i4 * 4;
    int dh  = (int)(i & 127);
    size_t r = i >> 7;
    int off = (int)(r & 255); r >>= 8;
    int h   = (int)(r & 15);  r >>= 4;
    int kv  = (int)(r & 1);
    int p   = (int)(r >> 1);

    int code = g_inv[p];
    float4 val;
    if (code < 0) {
        val = *(const float4*)(cache_in + i);
    } else {
        int b  = code >> 2;
        int lb = code & 3;
        int t  = b * SEQ + lb * PBS + off;
        const float* src = (kv == 0 ? g_k : g_v) + (size_t)t * DMODEL + h * DHEAD + dh;
        val = *(const float4*)src;
    }
    *(float4*)(cache_out + i) = val;
}

// =================== causal flash attention (fp32 SIMT) ====================
__global__ void flash_attn(const float* __restrict__ q, const float* __restrict__ k,
                           const float* __restrict__ v, float* __restrict__ o)
{
    extern __shared__ float sm[];
    float* Qs = sm;
    float* Ks = Qs + 64 * 132;
    float* Vs = Ks + 64 * 132;
    float* Ps = Vs + 64 * 132;

    const int qt = blockIdx.x;
    const int bh = blockIdx.y;
    const int b  = bh >> 4;
    const int h  = bh & 15;
    const int tid = threadIdx.x;
    const int ty = tid >> 4;
    const int tx = tid & 15;
    const int rq = ty * 4;
    const int ck = tx * 4;
    const int cd = tx * 8;
    const float scale = 0.08838834764831845f;

    const size_t base = ((size_t)b * SEQ) * DMODEL + (size_t)h * DHEAD;

#pragma unroll
    for (int it = 0; it < 8; it++) {
        int lin = tid + it * 256;
        int r = lin >> 5;
        int d = (lin & 31) << 2;
        *(float4*)&Qs[r * 132 + d] =
            *(const float4*)(q + base + (size_t)(qt * 64 + r) * DMODEL + d);
    }

    float m_i[4], l_i[4], oa[4][8];
#pragma unroll
    for (int i = 0; i < 4; i++) {
        m_i[i] = -1e30f; l_i[i] = 0.f;
#pragma unroll
        for (int c = 0; c < 8; c++) oa[i][c] = 0.f;
    }
    __syncthreads();

    for (int kt = 0; kt <= qt; kt++) {
#pragma unroll
        for (int it = 0; it < 8; it++) {
            int lin = tid + it * 256;
            int r = lin >> 5;
            int d = (lin & 31) << 2;
            size_t g = base + (size_t)(kt * 64 + r) * DMODEL + d;
            *(float4*)&Ks[r * 132 + d] = *(const float4*)(k + g);
            *(float4*)&Vs[r * 132 + d] = *(const float4*)(v + g);
        }
        __syncthreads();

        float s[4][4];
#pragma unroll
        for (int i = 0; i < 4; i++)
#pragma unroll
            for (int j = 0; j < 4; j++) s[i][j] = 0.f;

#pragma unroll 8
        for (int d0 = 0; d0 < DHEAD; d0 += 4) {
            float4 qv[4], kv4[4];
#pragma unroll
            for (int i = 0; i < 4; i++) qv[i]  = *(float4*)&Qs[(rq + i) * 132 + d0];
#pragma unroll
            for (int j = 0; j < 4; j++) kv4[j] = *(float4*)&Ks[(ck + j) * 132 + d0];
#pragma unroll
            for (int i = 0; i < 4; i++)
#pragma unroll
                for (int j = 0; j < 4; j++)
                    s[i][j] += qv[i].x * kv4[j].x + qv[i].y * kv4[j].y +
                               qv[i].z * kv4[j].z + qv[i].w * kv4[j].w;
        }

#pragma unroll
        for (int i = 0; i < 4; i++)
#pragma unroll
            for (int j = 0; j < 4; j++) {
                float val = s[i][j] * scale;
                if (kt == qt && (ck + j) > (rq + i)) val = -1e30f;
                s[i][j] = val;
            }

#pragma unroll
        for (int i = 0; i < 4; i++) {
            float rm = fmaxf(fmaxf(s[i][0], s[i][1]), fmaxf(s[i][2], s[i][3]));
#pragma unroll
            for (int off = 8; off > 0; off >>= 1)
                rm = fmaxf(rm, __shfl_xor_sync(0xffffffffu, rm, off));
            float mn = fmaxf(m_i[i], rm);
            float alpha = __expf(m_i[i] - mn);
            float rs = 0.f;
#pragma unroll
            for (int j = 0; j < 4; j++) {
                float p = __expf(s[i][j] - mn);
                Ps[(rq + i) * 68 + ck + j] = p;
                rs += p;
            }
#pragma unroll
            for (int off = 8; off > 0; off >>= 1)
                rs += __shfl_xor_sync(0xffffffffu, rs, off);
            l_i[i] = l_i[i] * alpha + rs;
            m_i[i] = mn;
#pragma unroll
            for (int c = 0; c < 8; c++) oa[i][c] *= alpha;
        }
        __syncthreads();

#pragma unroll 4
        for (int kk = 0; kk < 64; kk++) {
            float4 v0 = *(float4*)&Vs[kk * 132 + cd];
            float4 v1 = *(float4*)&Vs[kk * 132 + cd + 4];
#pragma unroll
            for (int i = 0; i < 4; i++) {
                float p = Ps[(rq + i) * 68 + kk];
                oa[i][0] += p * v0.x; oa[i][1] += p * v0.y;
                oa[i][2] += p * v0.z; oa[i][3] += p * v0.w;
                oa[i][4] += p * v1.x; oa[i][5] += p * v1.y;
                oa[i][6] += p * v1.z; oa[i][7] += p * v1.w;
            }
        }
        __syncthreads();
    }

#pragma unroll
    for (int i = 0; i < 4; i++) {
        float inv = 1.0f / l_i[i];
        float* dst = o + base + (size_t)(qt * 64 + rq + i) * DMODEL + cd;
        *(float4*)(dst)     = make_float4(oa[i][0] * inv, oa[i][1] * inv, oa[i][2] * inv, oa[i][3] * inv);
        *(float4*)(dst + 4) = make_float4(oa[i][4] * inv, oa[i][5] * inv, oa[i][6] * inv, oa[i][7] * inv);
    }
}

// =================== launch ================================================
extern "C" void kernel_launch(void* const* d_in, const int* in_sizes, int n_in,
                              void* d_out, int out_size)
{
    const float* x   = (const float*)d_in[0];
    const float* Wq  = (const float*)d_in[1];
    const float* Wk  = (const float*)d_in[2];
    const float* Wv  = (const float*)d_in[3];
    const float* Wo  = (const float*)d_in[4];
    const float* cin = (const float*)d_in[5];
    const int*   bt  = (const int*)d_in[7];

    float* out       = (float*)d_out;
    float* cache_out = out + (size_t)T_TOK * DMODEL;

    float *q, *k, *v, *attn;
    cudaGetSymbolAddress((void**)&q,    g_q);
    cudaGetSymbolAddress((void**)&k,    g_k);
    cudaGetSymbolAddress((void**)&v,    g_v);
    cudaGetSymbolAddress((void**)&attn, g_attn);
    __nv_bfloat16 *xh, *xl, *wh, *wl, *ah, *al;
    cudaGetSymbolAddress((void**)&xh, gx_hi);
    cudaGetSymbolAddress((void**)&xl, gx_lo);
    cudaGetSymbolAddress((void**)&wh, gw_hi);
    cudaGetSymbolAddress((void**)&wl, gw_lo);
    cudaGetSymbolAddress((void**)&ah, ga_hi);
    cudaGetSymbolAddress((void**)&al, ga_lo);

    const size_t fa_smem = (size_t)(3 * 64 * 132 + 64 * 68) * sizeof(float);
    cudaFuncSetAttribute(flash_attn, cudaFuncAttributeMaxDynamicSharedMemorySize,
                         (int)fa_smem);
    cudaFuncSetAttribute(gemm3x, cudaFuncAttributeMaxDynamicSharedMemorySize,
                         (int)GEMM_SMEM);

    // bf16 hi/lo splits (no-ops in fallback mode)
    const int xN4 = T_TOK * DMODEL / 4;
    const int wN4 = WSZ / 4;
    split_kernel<<<xN4 / 256, 256>>>(x, xh, xl, xN4);
    split_kernel<<<wN4 / 256, 256>>>(Wq, wh + (size_t)0 * WSZ, wl + (size_t)0 * WSZ, wN4);
    split_kernel<<<wN4 / 256, 256>>>(Wk, wh + (size_t)1 * WSZ, wl + (size_t)1 * WSZ, wN4);
    split_kernel<<<wN4 / 256, 256>>>(Wv, wh + (size_t)2 * WSZ, wl + (size_t)2 * WSZ, wN4);
    split_kernel<<<wN4 / 256, 256>>>(Wo, wh + (size_t)3 * WSZ, wl + (size_t)3 * WSZ, wN4);

    dim3 tgrid(DMODEL / 256, T_TOK / 128);   // tcgen05 grid (8, 64)
    dim3 fgrid(DMODEL / GBN, T_TOK / GBM);   // fallback grid (16, 64)

    // QKV projections — exactly one variant does work per build
    gemm3x<<<tgrid, 128, GEMM_SMEM>>>(xh, xl, wh + (size_t)0 * WSZ, wl + (size_t)0 * WSZ, q);
    gemm3x<<<tgrid, 128, GEMM_SMEM>>>(xh, xl, wh + (size_t)1 * WSZ, wl + (size_t)1 * WSZ, k);
    gemm3x<<<tgrid, 128, GEMM_SMEM>>>(xh, xl, wh + (size_t)2 * WSZ, wl + (size_t)2 * WSZ, v);
    gemm_nt<<<fgrid, 256>>>(x, Wq, q, T_TOK, DMODEL, DMODEL);
    gemm_nt<<<fgrid, 256>>>(x, Wk, k, T_TOK, DMODEL, DMODEL);
    gemm_nt<<<fgrid, 256>>>(x, Wv, v, T_TOK, DMODEL, DMODEL);

    trig_kernel<<<(SEQ * 64) / 256, 256>>>();
    build_inv<<<1, 64>>>(bt);

    rope_kernel<<<(T_TOK * NHEAD * 64) / 256, 256>>>();

    if ((size_t)out_size >= (size_t)T_TOK * DMODEL + (size_t)NPB * 2 * NHEAD * PBS * DHEAD) {
        cache_gather<<<((size_t)NPB * 2 * NHEAD * PBS * DHEAD / 4) / 256, 256>>>(cin, cache_out);
    }

    flash_attn<<<dim3(SEQ / 64, NSEQ * NHEAD), 256, fa_smem>>>(q, k, v, attn);

    // output projection
    split_kernel<<<xN4 / 256, 256>>>(attn, ah, al, xN4);
    gemm3x<<<tgrid, 128, GEMM_SMEM>>>(ah, al, wh + (size_t)3 * WSZ, wl + (size_t)3 * WSZ, out);
    gemm_nt<<<fgrid, 256>>>(attn, Wo, out, T_TOK, DMODEL, DMODEL);
}

// round 4
// speedup vs baseline: 1.9602x; 1.0023x over previous
#include <cuda_runtime.h>
#include <cuda_bf16.h>
#include <math.h>
#include <stdint.h>

#define T_TOK   8192
#define DMODEL  2048
#define NHEAD   16
#define DHEAD   128
#define SEQ     1024
#define NSEQ    8
#define PBS     256
#define NPB     64
#define BLKS_PER_SEQ 4
#define WSZ     (DMODEL * DMODEL)

// Device-pass arch gate: tcgen05 only exists in the 'a'-target compilation.
#if defined(__CUDA_ARCH__)
#  if defined(__CUDA_ARCH_FEAT_SM103_ALL) || defined(__CUDA_ARCH_FEAT_SM100_ALL) || \
      (defined(__CUDA_ARCH_SPECIFIC__) && (__CUDA_ARCH_SPECIFIC__ >= 1000))
#    define HAS_TCGEN05 1
#  endif
#endif

// ---------------- scratch (device globals; no runtime allocation) ----------
__device__ __align__(16) float g_q[(size_t)T_TOK * DMODEL];
__device__ __align__(16) float g_k[(size_t)T_TOK * DMODEL];
__device__ __align__(16) float g_v[(size_t)T_TOK * DMODEL];
__device__ __align__(16) float g_attn[(size_t)T_TOK * DMODEL];
__device__ __align__(16) float g_cos[SEQ * 64];
__device__ __align__(16) float g_sin[SEQ * 64];
__device__ int   g_inv[NPB];

// bf16 split operands (tcgen05 path only)
__device__ __align__(16) __nv_bfloat16 gx_hi[(size_t)T_TOK * DMODEL];
__device__ __align__(16) __nv_bfloat16 gx_lo[(size_t)T_TOK * DMODEL];
__device__ __align__(16) __nv_bfloat16 gw_hi[(size_t)4 * WSZ];
__device__ __align__(16) __nv_bfloat16 gw_lo[(size_t)4 * WSZ];
__device__ __align__(16) __nv_bfloat16 ga_hi[(size_t)T_TOK * DMODEL];
__device__ __align__(16) __nv_bfloat16 ga_lo[(size_t)T_TOK * DMODEL];

// =================== PTX helpers (arch-portable ones) ======================
__device__ __forceinline__ uint32_t smem_u32(const void* p) {
    uint32_t a;
    asm("{ .reg .u64 t; cvta.to.shared.u64 t, %1; cvt.u32.u64 %0, t; }"
        : "=r"(a) : "l"(p));
    return a;
}

__device__ __forceinline__ uint32_t elect_one_pred() {
    uint32_t pred;
    asm volatile(
        "{\n\t.reg .pred p;\n\telect.sync _|p, 0xFFFFFFFF;\n\t"
        "selp.b32 %0, 1, 0, p;\n\t}"
        : "=r"(pred));
    return pred;
}

#define MBAR_INIT(addr, cnt) \
    asm volatile("mbarrier.init.shared.b64 [%0], %1;" :: "r"(addr), "r"(cnt) : "memory")

#define MBAR_WAIT(addr, parity) do {                                          \
    uint32_t _mb = (addr); uint32_t _p = (parity); uint32_t _done;            \
    asm volatile("{\n\t.reg .pred p;\n\t"                                     \
        "mbarrier.try_wait.parity.acquire.cta.shared::cta.b64 p, [%1], %2;\n\t"\
        "selp.b32 %0, 1, 0, p;\n\t}"                                          \
        : "=r"(_done) : "r"(_mb), "r"(_p) : "memory");                        \
    if (!_done) {                                                             \
        asm volatile("{\n\t.reg .pred P1;\n\t"                                \
            "WL_%=:\n\t"                                                      \
            "mbarrier.try_wait.parity.acquire.cta.shared::cta.b64 P1, [%0], %1, 0x989680;\n\t" \
            "@P1 bra.uni WD_%=;\n\t"                                          \
            "bra.uni WL_%=;\n\t"                                              \
            "WD_%=:\n\t}"                                                     \
            :: "r"(_mb), "r"(_p) : "memory");                                 \
    }                                                                         \
} while (0)

__device__ __forceinline__ void cp16(uint32_t s, const void* g) {
    asm volatile("cp.async.cg.shared.global [%0], [%1], 16;" :: "r"(s), "l"(g));
}
__device__ __forceinline__ void cp_arrive_noinc(uint32_t mbar) {
    asm volatile("cp.async.mbarrier.arrive.noinc.shared::cta.b64 [%0];"
                 :: "r"(mbar) : "memory");
}

// =================== tcgen05-only helpers ==================================
#if defined(HAS_TCGEN05)
#define TC_ALLOC(sa, n) \
    asm volatile("tcgen05.alloc.cta_group::1.sync.aligned.shared::cta.b32 [%0], %1;" \
                 :: "r"((uint32_t)(sa)), "r"((uint32_t)(n)) : "memory")
#define TC_DEALLOC(t, n) \
    asm volatile("tcgen05.dealloc.cta_group::1.sync.aligned.b32 %0, %1;" :: "r"(t), "r"((uint32_t)(n)))
#define TC_RELINQ() \
    asm volatile("tcgen05.relinquish_alloc_permit.cta_group::1.sync.aligned;")
#define TC_COMMIT(mb) \
    asm volatile("tcgen05.commit.cta_group::1.mbarrier::arrive::one.shared::cluster.b64 [%0];" \
                 :: "r"((uint32_t)(mb)) : "memory")
#define TC_FENCE_AFTER() asm volatile("tcgen05.fence::after_thread_sync;" ::: "memory")
#define TC_WAIT_LD() asm volatile("tcgen05.wait::ld.sync.aligned;" ::: "memory")

#define TC_LD_X32(r, addr) \
    asm volatile("tcgen05.ld.sync.aligned.32x32b.x32.b32 " \
        "{%0, %1, %2, %3, %4, %5, %6, %7, %8, %9, %10, %11, %12, %13, %14, %15, " \
        " %16, %17, %18, %19, %20, %21, %22, %23, %24, %25, %26, %27, %28, %29, %30, %31}, [%32];" \
        : "=r"((r)[0]),  "=r"((r)[1]),  "=r"((r)[2]),  "=r"((r)[3]), \
          "=r"((r)[4]),  "=r"((r)[5]),  "=r"((r)[6]),  "=r"((r)[7]), \
          "=r"((r)[8]),  "=r"((r)[9]),  "=r"((r)[10]), "=r"((r)[11]), \
          "=r"((r)[12]), "=r"((r)[13]), "=r"((r)[14]), "=r"((r)[15]), \
          "=r"((r)[16]), "=r"((r)[17]), "=r"((r)[18]), "=r"((r)[19]), \
          "=r"((r)[20]), "=r"((r)[21]), "=r"((r)[22]), "=r"((r)[23]), \
          "=r"((r)[24]), "=r"((r)[25]), "=r"((r)[26]), "=r"((r)[27]), \
          "=r"((r)[28]), "=r"((r)[29]), "=r"((r)[30]), "=r"((r)[31]) \
        : "r"(addr))

__device__ __forceinline__ void mma_ss_bf16(uint32_t d, uint64_t ad, uint64_t bd,
                                            uint32_t idesc, uint32_t en) {
    asm volatile(
        "{\n\t.reg .pred p;\n\tsetp.ne.u32 p, %5, 0;\n\t"
        "tcgen05.mma.cta_group::1.kind::f16 [%0], %1, %2, %3, {%4, %4, %4, %4}, p;\n\t}"
        :: "r"(d), "l"(ad), "l"(bd), "r"(idesc), "r"(0u), "r"(en) : "memory");
}
#endif // HAS_TCGEN05

static constexpr uint64_t DESC_BASE_SW128 =
    (uint64_t(2)  << 61) | (uint64_t(1) << 46) | (uint64_t(64) << 32) | (uint64_t(1) << 16);
#define MK_DESC(a) (DESC_BASE_SW128 | ((uint64_t)((a) >> 4) & 0x3FFF))

// =================== split: fp32 -> bf16 hi + bf16 lo (tc path only) =======
__global__ void split_kernel(const float* __restrict__ src,
                             __nv_bfloat16* __restrict__ hi,
                             __nv_bfloat16* __restrict__ lo, int n4)
{
#if !defined(HAS_TCGEN05)
    return;   // fallback mode: tcgen05 GEMM never runs, split output unused
#else
    int i = blockIdx.x * blockDim.x + threadIdx.x;
    if (i >= n4) return;
    float4 v = ((const float4*)src)[i];
    __nv_bfloat16 h0 = __float2bfloat16(v.x);
    __nv_bfloat16 h1 = __float2bfloat16(v.y);
    __nv_bfloat16 h2 = __float2bfloat16(v.z);
    __nv_bfloat16 h3 = __float2bfloat16(v.w);
    __nv_bfloat16 l0 = __float2bfloat16(v.x - __bfloat162float(h0));
    __nv_bfloat16 l1 = __float2bfloat16(v.y - __bfloat162float(h1));
    __nv_bfloat16 l2 = __float2bfloat16(v.z - __bfloat162float(h2));
    __nv_bfloat16 l3 = __float2bfloat16(v.w - __bfloat162float(h3));
    uint2 hp, lp;
    unsigned short* hs = (unsigned short*)&hp;
    unsigned short* ls = (unsigned short*)&lp;
    hs[0] = reinterpret_cast<unsigned short&>(h0);
    hs[1] = reinterpret_cast<unsigned short&>(h1);
    hs[2] = reinterpret_cast<unsigned short&>(h2);
    hs[3] = reinterpret_cast<unsigned short&>(h3);
    ls[0] = reinterpret_cast<unsigned short&>(l0);
    ls[1] = reinterpret_cast<unsigned short&>(l1);
    ls[2] = reinterpret_cast<unsigned short&>(l2);
    ls[3] = reinterpret_cast<unsigned short&>(l3);
    ((uint2*)hi)[i] = hp;
    ((uint2*)lo)[i] = lp;
#endif
}

// =================== tcgen05 3xBF16 GEMM (a-pass only) =====================
// C[8192,2048] = A[8192,2048] @ B[2048,2048]^T, A=Ahi+Alo, B=Bhi+Blo
// CTA tile M=128, N=256; K in chunks of 64 (128B SW128 rows); 2-stage cp.async
#define STAGE_BYTES 98304u
#define BAR_OFF     196608u
#define GEMM_SMEM   196672u

static constexpr uint32_t IDESC_BF16 =
    (1u << 4) | (1u << 7) | (1u << 10) | ((256u / 8) << 17) | ((128u / 16) << 24);

__global__ __launch_bounds__(128, 1)
void gemm3x(const __nv_bfloat16* __restrict__ Ahi, const __nv_bfloat16* __restrict__ Alo,
            const __nv_bfloat16* __restrict__ Bhi, const __nv_bfloat16* __restrict__ Blo,
            float* __restrict__ C)
{
#if !defined(HAS_TCGEN05)
    return;   // non-'a' compilation: gemm_nt fallback does the work instead
#else
    extern __shared__ char smem[];
    const uint32_t sb = smem_u32(smem);
    const int tid = threadIdx.x;
    const int bn = blockIdx.x;   // 0..7
    const int bm = blockIdx.y;   // 0..63

    const uint32_t FULL  = sb + BAR_OFF;
    const uint32_t EMPTY = sb + BAR_OFF + 16;
    const uint32_t DONE  = sb + BAR_OFF + 32;
    const uint32_t TPTR  = sb + BAR_OFF + 40;

    if (tid == 0) {
        MBAR_INIT(FULL + 0, 96);  MBAR_INIT(FULL + 8, 96);
        MBAR_INIT(EMPTY + 0, 1);  MBAR_INIT(EMPTY + 8, 1);
        MBAR_INIT(DONE, 1);
    }
    if (tid < 32) TC_ALLOC(TPTR, 256);
    __syncthreads();
    uint32_t tmem;
    asm volatile("ld.shared.b32 %0, [%1];" : "=r"(tmem) : "r"(TPTR));

    if (tid < 32) {
        if (elect_one_pred()) {
            for (int kt = 0; kt < 32; kt++) {
                const int st = kt & 1;
                MBAR_WAIT(FULL + st * 8, (kt >> 1) & 1);
                asm volatile("fence.proxy.async.shared::cta;" ::: "memory");
                const uint32_t so = sb + st * STAGE_BYTES;
                const uint64_t ah = MK_DESC(so);
                const uint64_t al = MK_DESC(so + 16384u);
                const uint64_t bh = MK_DESC(so + 32768u);
                const uint64_t bl = MK_DESC(so + 65536u);
#pragma unroll
                for (int ks = 0; ks < 4; ks++) {
                    mma_ss_bf16(tmem, ah + ks * 2, bh + ks * 2, IDESC_BF16,
                                (kt | ks) ? 1u : 0u);
                    mma_ss_bf16(tmem, al + ks * 2, bh + ks * 2, IDESC_BF16, 1u);
                    mma_ss_bf16(tmem, ah + ks * 2, bl + ks * 2, IDESC_BF16, 1u);
                }
                TC_COMMIT(EMPTY + st * 8);
            }
            TC_COMMIT(DONE);
        }
    } else {
        const int t = tid - 32;
        for (int lk = 0; lk < 32; lk++) {
            const int st = lk & 1;
            if (lk >= 2) MBAR_WAIT(EMPTY + st * 8, ((lk >> 1) - 1) & 1);
            const uint32_t so = sb + st * STAGE_BYTES;
            const int k0 = lk * 64;
            if (t < 32) {
                const int r0 = t * 4;
#pragma unroll
                for (int rr = 0; rr < 4; rr++) {
                    const int r = r0 + rr;
                    const size_t gofs = (size_t)(bm * 128 + r) * DMODEL + k0;
                    const __nv_bfloat16* gh = Ahi + gofs;
                    const __nv_bfloat16* gl = Alo + gofs;
                    const uint32_t srow = so + r * 128;
#pragma unroll
                    for (int c = 0; c < 8; c++) {
                        const uint32_t sw = (uint32_t)((c ^ (r & 7)) << 4);
                        cp16(srow + sw,          gh + c * 8);
                        cp16(srow + 16384u + sw, gl + c * 8);
                    }
                }
            } else {
                const int r0 = (t - 32) * 4;
#pragma unroll
                for (int rr = 0; rr < 4; rr++) {
                    const int r = r0 + rr;
                    const size_t gofs = (size_t)(bn * 256 + r) * DMODEL + k0;
                    const __nv_bfloat16* gh = Bhi + gofs;
                    const __nv_bfloat16* gl = Blo + gofs;
                    const uint32_t srow = so + 32768u + r * 128;
#pragma unroll
                    for (int c = 0; c < 8; c++) {
                        const uint32_t sw = (uint32_t)((c ^ (r & 7)) << 4);
                        cp16(srow + sw,          gh + c * 8);
                        cp16(srow + 32768u + sw, gl + c * 8);
                    }
                }
            }
            cp_arrive_noinc(FULL + st * 8);
        }
    }

    __syncthreads();
    MBAR_WAIT(DONE, 0);
    TC_FENCE_AFTER();

    const int w = tid >> 5, l = tid & 31;
    const size_t row = (size_t)(bm * 128 + w * 32 + l);
#pragma unroll 1
    for (int cb = 0; cb < 256; cb += 32) {
        uint32_t r[32];
        TC_LD_X32(r, tmem + cb);
        TC_WAIT_LD();
        float* dst = C + row * DMODEL + bn * 256 + cb;
#pragma unroll
        for (int j = 0; j < 32; j += 4) {
            float4 v = make_float4(__uint_as_float(r[j]),     __uint_as_float(r[j + 1]),
                                   __uint_as_float(r[j + 2]), __uint_as_float(r[j + 3]));
            *(float4*)(dst + j) = v;
        }
    }

    __syncthreads();
    if (tid < 32) {
        TC_RELINQ();
        TC_DEALLOC(tmem, 256);
    }
#endif // HAS_TCGEN05
}

// =================== fp32 SIMT GEMM fallback (non-'a' pass only) ============
#define GBM 128
#define GBN 128
#define GBK 16

__global__ __launch_bounds__(256, 2)
void gemm_nt(const float* __restrict__ A, const float* __restrict__ B,
             float* __restrict__ C, int M, int N, int K)
{
#if defined(HAS_TCGEN05)
    return;   // 'a' pass: gemm3x does the work instead
#else
    __shared__ float As[GBK][GBM + 4];
    __shared__ float Bs[GBK][GBN + 4];

    const int tid = threadIdx.x;
    const int bn  = blockIdx.x;
    const int bm  = blockIdx.y;

    const float* Ab = A + (size_t)bm * GBM * K;
    const float* Bb = B + (size_t)bn * GBN * K;

    const int ty  = tid >> 4;
    const int tx  = tid & 15;
    const int row = ty * 8;
    const int col = tx * 8;

    float acc[8][8];
#pragma unroll
    for (int i = 0; i < 8; i++)
#pragma unroll
        for (int j = 0; j < 8; j++) acc[i][j] = 0.f;

    for (int k0 = 0; k0 < K; k0 += GBK) {
#pragma unroll
        for (int it = 0; it < 2; it++) {
            int lin = tid + it * 256;
            int m   = lin >> 2;
            int kq  = (lin & 3) << 2;
            float4 a = *(const float4*)(Ab + (size_t)m * K + k0 + kq);
            As[kq + 0][m] = a.x; As[kq + 1][m] = a.y;
            As[kq + 2][m] = a.z; As[kq + 3][m] = a.w;
            float4 b = *(const float4*)(Bb + (size_t)m * K + k0 + kq);
            Bs[kq + 0][m] = b.x; Bs[kq + 1][m] = b.y;
            Bs[kq + 2][m] = b.z; Bs[kq + 3][m] = b.w;
        }
        __syncthreads();

#pragma unroll
        for (int k = 0; k < GBK; k++) {
            float a[8], b[8];
            *(float4*)(a)     = *(const float4*)&As[k][row];
            *(float4*)(a + 4) = *(const float4*)&As[k][row + 4];
            *(float4*)(b)     = *(const float4*)&Bs[k][col];
            *(float4*)(b + 4) = *(const float4*)&Bs[k][col + 4];
#pragma unroll
            for (int i = 0; i < 8; i++)
#pragma unroll
                for (int j = 0; j < 8; j++) acc[i][j] += a[i] * b[j];
        }
        __syncthreads();
    }

#pragma unroll
    for (int i = 0; i < 8; i++) {
        float* Cr = C + (size_t)(bm * GBM + row + i) * N + bn * GBN + col;
        *(float4*)(Cr)     = make_float4(acc[i][0], acc[i][1], acc[i][2], acc[i][3]);
        *(float4*)(Cr + 4) = make_float4(acc[i][4], acc[i][5], acc[i][6], acc[i][7]);
    }
#endif
}

// =================== trig table ============================================
__global__ void trig_kernel()
{
    int idx = blockIdx.x * blockDim.x + threadIdx.x;
    int j   = idx & 63;
    int pos = idx >> 6;
    float inv_freq = expf(-(float)(2 * j) * (1.0f / 128.0f) * logf(10000.0f));
    float ang = (float)pos * inv_freq;
    float s, c;
    sincosf(ang, &s, &c);
    g_cos[idx] = c;
    g_sin[idx] = s;
}

// =================== RoPE in-place on g_q, g_k =============================
__global__ void rope_kernel()
{
    int idx = blockIdx.x * blockDim.x + threadIdx.x;
    int j = idx & 63;
    int h = (idx >> 6) & 15;
    int t = idx >> 10;
    int pos = t & (SEQ - 1);
    float c = g_cos[pos * 64 + j];
    float s = g_sin[pos * 64 + j];
    size_t o0 = (size_t)t * DMODEL + h * DHEAD + j;
    size_t o1 = o0 + 64;
    float q0 = g_q[o0], q1 = g_q[o1];
    g_q[o0] = q0 * c - q1 * s;
    g_q[o1] = q1 * c + q0 * s;
    float k0 = g_k[o0], k1 = g_k[o1];
    g_k[o0] = k0 * c - k1 * s;
    g_k[o1] = k1 * c + k0 * s;
}

// =================== inverse block table ===================================
__global__ void build_inv(const int* __restrict__ bt)
{
    int i = threadIdx.x;
    if (i < NPB) g_inv[i] = -1;
    __syncthreads();
    if (i < NSEQ * BLKS_PER_SEQ) {
        int p = bt[i];
        g_inv[p] = i;
    }
}

// =================== paged-KV cache gather =================================
__global__ void cache_gather(const float* __restrict__ cache_in,
                             float* __restrict__ cache_out)
{
    size_t i4 = (size_t)blockIdx.x * 256 + threadIdx.x;
    size_t i  = i4 * 4;
    int dh  = (int)(i & 127);
    size_t r = i >> 7;
    int off = (int)(r & 255); r >>= 8;
    int h   = (int)(r & 15);  r >>= 4;
    int kv  = (int)(r & 1);
    int p   = (int)(r >> 1);

    int code = g_inv[p];
    float4 val;
    if (code < 0) {
        val = *(const float4*)(cache_in + i);
    } else {
        int b  = code >> 2;
        int lb = code & 3;
        int t  = b * SEQ + lb * PBS + off;
        const float* src = (kv == 0 ? g_k : g_v) + (size_t)t * DMODEL + h * DHEAD + dh;
        val = *(const float4*)src;
    }
    *(float4*)(cache_out + i) = val;
}

// =================== causal flash attention (fp32 SIMT) ====================
__global__ void flash_attn(const float* __restrict__ q, const float* __restrict__ k,
                           const float* __restrict__ v, float* __restrict__ o)
{
    extern __shared__ float sm[];
    float* Qs = sm;
    float* Ks = Qs + 64 * 132;
    float* Vs = Ks + 64 * 132;
    float* Ps = Vs + 64 * 132;

    const int qt = blockIdx.x;
    const int bh = blockIdx.y;
    const int b  = bh >> 4;
    const int h  = bh & 15;
    const int tid = threadIdx.x;
    const int ty = tid >> 4;
    const int tx = tid & 15;
    const int rq = ty * 4;
    const int ck = tx * 4;
    const int cd = tx * 8;
    const float scale = 0.08838834764831845f;

    const size_t base = ((size_t)b * SEQ) * DMODEL + (size_t)h * DHEAD;

#pragma unroll
    for (int it = 0; it < 8; it++) {
        int lin = tid + it * 256;
        int r = lin >> 5;
        int d = (lin & 31) << 2;
        *(float4*)&Qs[r * 132 + d] =
            *(const float4*)(q + base + (size_t)(qt * 64 + r) * DMODEL + d);
    }

    float m_i[4], l_i[4], oa[4][8];
#pragma unroll
    for (int i = 0; i < 4; i++) {
        m_i[i] = -1e30f; l_i[i] = 0.f;
#pragma unroll
        for (int c = 0; c < 8; c++) oa[i][c] = 0.f;
    }
    __syncthreads();

    for (int kt = 0; kt <= qt; kt++) {
#pragma unroll
        for (int it = 0; it < 8; it++) {
            int lin = tid + it * 256;
            int r = lin >> 5;
            int d = (lin & 31) << 2;
            size_t g = base + (size_t)(kt * 64 + r) * DMODEL + d;
            *(float4*)&Ks[r * 132 + d] = *(const float4*)(k + g);
            *(float4*)&Vs[r * 132 + d] = *(const float4*)(v + g);
        }
        __syncthreads();

        float s[4][4];
#pragma unroll
        for (int i = 0; i < 4; i++)
#pragma unroll
            for (int j = 0; j < 4; j++) s[i][j] = 0.f;

#pragma unroll 8
        for (int d0 = 0; d0 < DHEAD; d0 += 4) {
            float4 qv[4], kv4[4];
#pragma unroll
            for (int i = 0; i < 4; i++) qv[i]  = *(float4*)&Qs[(rq + i) * 132 + d0];
#pragma unroll
            for (int j = 0; j < 4; j++) kv4[j] = *(float4*)&Ks[(ck + j) * 132 + d0];
#pragma unroll
            for (int i = 0; i < 4; i++)
#pragma unroll
                for (int j = 0; j < 4; j++)
                    s[i][j] += qv[i].x * kv4[j].x + qv[i].y * kv4[j].y +
                               qv[i].z * kv4[j].z + qv[i].w * kv4[j].w;
        }

#pragma unroll
        for (int i = 0; i < 4; i++)
#pragma unroll
            for (int j = 0; j < 4; j++) {
                float val = s[i][j] * scale;
                if (kt == qt && (ck + j) > (rq + i)) val = -1e30f;
                s[i][j] = val;
            }

#pragma unroll
        for (int i = 0; i < 4; i++) {
            float rm = fmaxf(fmaxf(s[i][0], s[i][1]), fmaxf(s[i][2], s[i][3]));
#pragma unroll
            for (int off = 8; off > 0; off >>= 1)
                rm = fmaxf(rm, __shfl_xor_sync(0xffffffffu, rm, off));
            float mn = fmaxf(m_i[i], rm);
            float alpha = __expf(m_i[i] - mn);
            float rs = 0.f;
#pragma unroll
            for (int j = 0; j < 4; j++) {
                float p = __expf(s[i][j] - mn);
                Ps[(rq + i) * 68 + ck + j] = p;
                rs += p;
            }
#pragma unroll
            for (int off = 8; off > 0; off >>= 1)
                rs += __shfl_xor_sync(0xffffffffu, rs, off);
            l_i[i] = l_i[i] * alpha + rs;
            m_i[i] = mn;
#pragma unroll
            for (int c = 0; c < 8; c++) oa[i][c] *= alpha;
        }
        __syncthreads();

#pragma unroll 4
        for (int kk = 0; kk < 64; kk++) {
            float4 v0 = *(float4*)&Vs[kk * 132 + cd];
            float4 v1 = *(float4*)&Vs[kk * 132 + cd + 4];
#pragma unroll
            for (int i = 0; i < 4; i++) {
                float p = Ps[(rq + i) * 68 + kk];
                oa[i][0] += p * v0.x; oa[i][1] += p * v0.y;
                oa[i][2] += p * v0.z; oa[i][3] += p * v0.w;
                oa[i][4] += p * v1.x; oa[i][5] += p * v1.y;
                oa[i][6] += p * v1.z; oa[i][7] += p * v1.w;
            }
        }
        __syncthreads();
    }

#pragma unroll
    for (int i = 0; i < 4; i++) {
        float inv = 1.0f / l_i[i];
        float* dst = o + base + (size_t)(qt * 64 + rq + i) * DMODEL + cd;
        *(float4*)(dst)     = make_float4(oa[i][0] * inv, oa[i][1] * inv, oa[i][2] * inv, oa[i][3] * inv);
        *(float4*)(dst + 4) = make_float4(oa[i][4] * inv, oa[i][5] * inv, oa[i][6] * inv, oa[i][7] * inv);
    }
}

// =================== launch ================================================
extern "C" void kernel_launch(void* const* d_in, const int* in_sizes, int n_in,
                              void* d_out, int out_size)
{
    const float* x   = (const float*)d_in[0];
    const float* Wq  = (const float*)d_in[1];
    const float* Wk  = (const float*)d_in[2];
    const float* Wv  = (const float*)d_in[3];
    const float* Wo  = (const float*)d_in[4];
    const float* cin = (const float*)d_in[5];
    const int*   bt  = (const int*)d_in[7];

    float* out       = (float*)d_out;
    float* cache_out = out + (size_t)T_TOK * DMODEL;

    float *q, *k, *v, *attn;
    cudaGetSymbolAddress((void**)&q,    g_q);
    cudaGetSymbolAddress((void**)&k,    g_k);
    cudaGetSymbolAddress((void**)&v,    g_v);
    cudaGetSymbolAddress((void**)&attn, g_attn);
    __nv_bfloat16 *xh, *xl, *wh, *wl, *ah, *al;
    cudaGetSymbolAddress((void**)&xh, gx_hi);
    cudaGetSymbolAddress((void**)&xl, gx_lo);
    cudaGetSymbolAddress((void**)&wh, gw_hi);
    cudaGetSymbolAddress((void**)&wl, gw_lo);
    cudaGetSymbolAddress((void**)&ah, ga_hi);
    cudaGetSymbolAddress((void**)&al, ga_lo);

    const size_t fa_smem = (size_t)(3 * 64 * 132 + 64 * 68) * sizeof(float);
    cudaFuncSetAttribute(flash_attn, cudaFuncAttributeMaxDynamicSharedMemorySize,
                         (int)fa_smem);
    cudaFuncSetAttribute(gemm3x, cudaFuncAttributeMaxDynamicSharedMemorySize,
                         (int)GEMM_SMEM);

    // bf16 hi/lo splits (no-ops in fallback mode)
    const int xN4 = T_TOK * DMODEL / 4;
    const int wN4 = WSZ / 4;
    split_kernel<<<xN4 / 256, 256>>>(x, xh, xl, xN4);
    split_kernel<<<wN4 / 256, 256>>>(Wq, wh + (size_t)0 * WSZ, wl + (size_t)0 * WSZ, wN4);
    split_kernel<<<wN4 / 256, 256>>>(Wk, wh + (size_t)1 * WSZ, wl + (size_t)1 * WSZ, wN4);
    split_kernel<<<wN4 / 256, 256>>>(Wv, wh + (size_t)2 * WSZ, wl + (size_t)2 * WSZ, wN4);
    split_kernel<<<wN4 / 256, 256>>>(Wo, wh + (size_t)3 * WSZ, wl + (size_t)3 * WSZ, wN4);

    dim3 tgrid(DMODEL / 256, T_TOK / 128);   // tcgen05 grid (8, 64)
    dim3 fgrid(DMODEL / GBN, T_TOK / GBM);   // fallback grid (16, 64)

    // QKV projections — exactly one variant does work per build
    gemm3x<<<tgrid, 128, GEMM_SMEM>>>(xh, xl, wh + (size_t)0 * WSZ, wl + (size_t)0 * WSZ, q);
    gemm3x<<<tgrid, 128, GEMM_SMEM>>>(xh, xl, wh + (size_t)1 * WSZ, wl + (size_t)1 * WSZ, k);
    gemm3x<<<tgrid, 128, GEMM_SMEM>>>(xh, xl, wh + (size_t)2 * WSZ, wl + (size_t)2 * WSZ, v);
    gemm_nt<<<fgrid, 256>>>(x, Wq, q, T_TOK, DMODEL, DMODEL);
    gemm_nt<<<fgrid, 256>>>(x, Wk, k, T_TOK, DMODEL, DMODEL);
    gemm_nt<<<fgrid, 256>>>(x, Wv, v, T_TOK, DMODEL, DMODEL);

    trig_kernel<<<(SEQ * 64) / 256, 256>>>();
    build_inv<<<1, 64>>>(bt);

    rope_kernel<<<(T_TOK * NHEAD * 64) / 256, 256>>>();

    if ((size_t)out_size >= (size_t)T_TOK * DMODEL + (size_t)NPB * 2 * NHEAD * PBS * DHEAD) {
        cache_gather<<<((size_t)NPB * 2 * NHEAD * PBS * DHEAD / 4) / 256, 256>>>(cin, cache_out);
    }

    flash_attn<<<dim3(SEQ / 64, NSEQ * NHEAD), 256, fa_smem>>>(q, k, v, attn);

    // output projection
    split_kernel<<<xN4 / 256, 256>>>(attn, ah, al, xN4);
    gemm3x<<<tgrid, 128, GEMM_SMEM>>>(ah, al, wh + (size_t)3 * WSZ, wl + (size_t)3 * WSZ, out);
    gemm_nt<<<fgrid, 256>>>(attn, Wo, out, T_TOK, DMODEL, DMODEL);
}